// round 7
// baseline (speedup 1.0000x reference)
#include <cuda_runtime.h>
#include <math.h>

#define BATCH 64
#define NPART 512
#define BLK   1024               // 32 warps: 16 target-side, 16 reco-side
#define GRID  BATCH              // one CTA per batch
#define NGRP  16                 // binning groups per side (one per warp)

// Scratch (no allocation allowed).
__device__ float g_batch[BATCH][2];   // per-batch (nz, zz)
__device__ int   g_ticket;            // global arrival counter (reset in-kernel)

__global__ __launch_bounds__(BLK)
void chamfer_fused(const float4* __restrict__ target,
                   const float4* __restrict__ reco,
                   const int*    __restrict__ in_pid,
                   const int*    __restrict__ out_pid,
                   float* __restrict__ out, int out_size)
{
    __shared__ float4 sT[NPART], sR[NPART];      // class-compacted particles
    __shared__ float  sQT[NPART], sQR[NPART];    // 0.5*|p|^2 (compacted)
    __shared__ int    bin[2][NGRP][5];           // group counts -> group prefixes
    __shared__ int    tot[2][5];
    __shared__ int    off[2][6];                 // class offsets per side
    __shared__ float  acc[2][5];                 // per-class chamfer sums (A=0,B=1)
    __shared__ float  nsum[2][5];                // per-class norm sums (t=0,r=1)
    __shared__ float  snz[BATCH], szz[BATCH];    // final gather (last CTA)
    __shared__ int    fl;

    const int b    = blockIdx.x;
    const int tid  = threadIdx.x;
    const int side = tid >> 9;           // 0 = target, 1 = reco
    const int i    = tid & (NPART - 1);  // particle index within side
    const int w    = tid >> 5;
    const int g    = w & (NGRP - 1);     // group within side
    const int lane = tid & 31;
    const unsigned lt = (1u << lane) - 1u;

    if (tid < 10) { acc[0][tid % 5 + 5 * (tid / 5) - 5 * (tid / 5)] = 0.f; }
    // simpler explicit inits:
    if (tid < 10) { (&acc[0][0])[tid] = 0.f; (&nsum[0][0])[tid] = 0.f; }
    if (tid < 2 * NGRP * 5) (&bin[0][0][0])[tid] = 0;
    __syncthreads();

    // ---- Load (1 particle per thread) + atomic-free binning + norm sums ----
    const float4 v = side ? reco[b * NPART + i] : target[b * NPART + i];
    const int    p = side ? out_pid[b * NPART + i] : in_pid[b * NPART + i];

    const unsigned mm = __match_any_sync(0xffffffffu, p);  // warp is side-uniform
    const int rk = __popc(mm & lt);
    if (rk == 0) bin[side][g][p] = __popc(mm);

    const float q2 = v.x*v.x + v.y*v.y + v.z*v.z + v.w*v.w;
    atomicAdd(&nsum[side][p], sqrtf(q2));
    __syncthreads();

    // ---- Exclusive prefix over the 16 groups, per class (register-resident) ----
    if (tid < 10) {
        const int sd = tid / 5, q = tid % 5;
        int vv[NGRP];
#pragma unroll
        for (int gg = 0; gg < NGRP; gg++) vv[gg] = bin[sd][gg][q];
        int run = 0;
#pragma unroll
        for (int gg = 0; gg < NGRP; gg++) { const int c = vv[gg]; bin[sd][gg][q] = run; run += c; }
        tot[sd][q] = run;
    }
    __syncthreads();
    if (tid < 2) {
        int a = 0;
#pragma unroll
        for (int q = 0; q < 5; q++) { off[tid][q] = a; a += tot[tid][q]; }
        off[tid][5] = a;
    }
    __syncthreads();

    // ---- Deterministic scatter: particle + half-sq-norm ----
    {
        const int ix = off[side][p] + bin[side][g][p] + rk;
        if (side) { sR[ix] = v; sQR[ix] = 0.5f * q2; }
        else      { sT[ix] = v; sQT[ix] = 0.5f * q2; }
    }
    __syncthreads();

    // ---- Main work: one item per thread (classes 1..4 only) ----
    // min_j |x-y_j|^2 = |x|^2 + 2*min_j(h_j - x.y_j),  h_j = 0.5|y_j|^2
    const int nA = NPART - off[0][1];
    const int nB = NPART - off[1][1];
    const int m  = tid;                  // BLK = 1024 >= nA + nB

    if (m < nA + nB) {
        const bool passA = (m < nA);
        int k = passA ? (off[0][1] + m) : (off[1][1] + (m - nA));
        const int* off_self  = passA ? off[0] : off[1];
        const int* off_other = passA ? off[1] : off[0];

        int q = 1;
        while (k >= off_self[q + 1]) q++;

        const int jb = off_other[q], je = off_other[q + 1];
        if (jb != je) {
            const float4  x     = passA ? sT[k]  : sR[k];
            const float   xsq   = 2.f * (passA ? sQT[k] : sQR[k]);
            const float4* other = passA ? sR  : sT;
            const float*  hoth  = passA ? sQR : sQT;
            const float nx = -x.x, ny = -x.y, nz = -x.z, nw = -x.w;

            float ms0 = INFINITY, ms1 = INFINITY;
            int j = jb;
            if ((je - jb) & 1) {
                const float4 y = other[j];
                ms0 = fmaf(nx, y.x, fmaf(ny, y.y, fmaf(nz, y.z, fmaf(nw, y.w, hoth[j]))));
                j++;
            }
#pragma unroll 4
            for (; j < je; j += 2) {
                const float4 y0 = other[j];
                const float4 y1 = other[j + 1];
                const float s0 = fmaf(nx, y0.x, fmaf(ny, y0.y, fmaf(nz, y0.z, fmaf(nw, y0.w, hoth[j]))));
                const float s1 = fmaf(nx, y1.x, fmaf(ny, y1.y, fmaf(nz, y1.z, fmaf(nw, y1.w, hoth[j + 1]))));
                ms0 = fminf(ms0, s0);
                ms1 = fminf(ms1, s1);
            }
            const float ms = fminf(ms0, ms1);
            const float d2 = fmaxf(fmaf(2.f, ms, xsq), 0.f);
            atomicAdd(&acc[passA ? 0 : 1][q], sqrtf(d2));
        }
    }
    __syncthreads();

    // ---- Per-batch scalars: single thread, single fence, single ticket ----
    if (tid == 0) {
        float nzsum = 0.f;
#pragma unroll
        for (int q = 1; q < 5; q++) {
            const float cx = (float)(off[0][q + 1] - off[0][q]);
            const float cy = (float)(off[1][q + 1] - off[1][q]);
            float per;
            if (cy == 0.f)      per = nsum[0][q] / fmaxf(1.f, cx);
            else if (cx == 0.f) per = nsum[1][q] / fmaxf(1.f, cy);
            else                per = 0.5f * (acc[0][q] / fmaxf(1.f, cy)
                                            + acc[1][q] / fmaxf(1.f, cx));
            nzsum += per;
        }
        g_batch[b][0] = nzsum;
        g_batch[b][1] = nsum[1][0] / fmaxf(1.f, (float)(off[1][1] - off[1][0]));
        __threadfence();                           // order STG before ticket
        fl = (atomicAdd(&g_ticket, 1) == GRID - 1);
    }
    __syncthreads();
    if (!fl) return;

    // ---- Last CTA: final combine over 64 batches ----
    __threadfence();                               // acquire all g_batch
    if (tid < BATCH) {
        const float2 vv = __ldcg((const float2*)&g_batch[tid][0]);
        snz[tid] = vv.x;
        szz[tid] = vv.y;
    }
    __syncthreads();
    if (tid < 32) {
        float a = snz[tid] + snz[tid + 32];
        float c = szz[tid] + szz[tid + 32];
#pragma unroll
        for (int o = 16; o; o >>= 1) {
            a += __shfl_down_sync(0xffffffffu, a, o);
            c += __shfl_down_sync(0xffffffffu, c, o);
        }
        if (tid == 0) {
            out[0] = a / (float)BATCH;
            if (out_size > 1) out[1] = c / (float)BATCH;
            g_ticket = 0;                          // reset for next graph replay
        }
    }
}

extern "C" void kernel_launch(void* const* d_in, const int* in_sizes, int n_in,
                              void* d_out, int out_size)
{
    const float4* target = (const float4*)d_in[0];
    const float4* reco   = (const float4*)d_in[1];
    const int*    ipid   = (const int*)d_in[2];
    const int*    opid   = (const int*)d_in[3];
    float*        out    = (float*)d_out;
    (void)in_sizes; (void)n_in;

    chamfer_fused<<<GRID, BLK>>>(target, reco, ipid, opid, out, out_size);
}

// round 8
// speedup vs baseline: 1.2240x; 1.2240x over previous
#include <cuda_runtime.h>
#include <cooperative_groups.h>
#include <math.h>

namespace cg = cooperative_groups;

#define BATCH 64
#define NPART 512
#define SPLIT 2
#define BLK   512
#define NW    (BLK / 32)         // 16 warps; each warp is one binning group
#define NGRP  NW
#define GRID  (BATCH * SPLIT)    // 128 CTAs = 64 clusters of 2

// Scratch (no allocation allowed).
__device__ float2 g_batch[BATCH];     // per-batch (nz, zz)
__device__ int    g_ticket;           // global arrival counter (reset in-kernel)

__global__ __launch_bounds__(BLK) __cluster_dims__(2, 1, 1)
void chamfer_fused(const float4* __restrict__ target,
                   const float4* __restrict__ reco,
                   const int*    __restrict__ in_pid,
                   const int*    __restrict__ out_pid,
                   float* __restrict__ out, int out_size)
{
    __shared__ float4 sT[NPART], sR[NPART];      // class-compacted particles
    __shared__ float  sQT[NPART], sQR[NPART];    // 0.5*|p|^2 (compacted)
    __shared__ int    bX[NGRP][5], bY[NGRP][5];  // group counts -> group prefixes
    __shared__ int    totX[5], totY[5];
    __shared__ int    offX[6], offY[6];
    __shared__ float  xacc[10];                  // exported: [0..4]=accA, [5..9]=accB
    __shared__ float  mNT[5], mNR[5];            // per-class norm sums (rank0 only)
    __shared__ float  snz[BATCH], szz[BATCH];    // final gather (last CTA)
    __shared__ int    fl;

    cg::cluster_group cluster = cg::this_cluster();

    const int b    = blockIdx.x >> 1;
    const int s    = blockIdx.x & 1;             // cluster rank
    const int tid  = threadIdx.x;
    const int w    = tid >> 5;
    const int lane = tid & 31;
    const unsigned lt = (1u << lane) - 1u;

    if (tid < 10) xacc[tid] = 0.f;
    if (tid < NGRP * 5) { (&bX[0][0])[tid] = 0; (&bY[0][0])[tid] = 0; }
    __syncthreads();

    const float4* Tb  = target  + b * NPART;
    const float4* Rb  = reco    + b * NPART;
    const int*    IPb = in_pid  + b * NPART;
    const int*    OPb = out_pid + b * NPART;

    // ---- Load (1 target + 1 reco per thread) + atomic-free binning ----
    const float4 tv = Tb[tid];
    const float4 rv = Rb[tid];
    const int    tp = IPb[tid];
    const int    rp = OPb[tid];
    const unsigned mX = __match_any_sync(0xffffffffu, tp);
    const unsigned mY = __match_any_sync(0xffffffffu, rp);
    const int rkX = __popc(mX & lt);
    const int rkY = __popc(mY & lt);
    if (rkX == 0) bX[w][tp] = __popc(mX);
    if (rkY == 0) bY[w][rp] = __popc(mY);
    __syncthreads();

    // ---- Exclusive prefix over the 16 groups, per class (register-resident) ----
    if (tid < 10) {
        const int side = tid / 5, q = tid % 5;
        int (*bb)[5] = side ? bY : bX;
        int v[NGRP];
#pragma unroll
        for (int g = 0; g < NGRP; g++) v[g] = bb[g][q];
        int run = 0;
#pragma unroll
        for (int g = 0; g < NGRP; g++) { const int c = v[g]; bb[g][q] = run; run += c; }
        if (side) totY[q] = run; else totX[q] = run;
    }
    __syncthreads();
    if (tid == 0) { int a = 0; for (int q = 0; q < 5; q++) { offX[q] = a; a += totX[q]; } offX[5] = a; }
    if (tid == 1) { int a = 0; for (int q = 0; q < 5; q++) { offY[q] = a; a += totY[q]; } offY[5] = a; }
    __syncthreads();

    // ---- Deterministic scatter (no atomics): particle + half-sq-norm ----
    {
        const int ix = offX[tp] + bX[w][tp] + rkX;
        const int iy = offY[rp] + bY[w][rp] + rkY;
        sT[ix] = tv;  sQT[ix] = 0.5f * (tv.x*tv.x + tv.y*tv.y + tv.z*tv.z + tv.w*tv.w);
        sR[iy] = rv;  sQR[iy] = 0.5f * (rv.x*rv.x + rv.y*rv.y + rv.z*rv.z + rv.w*rv.w);
    }
    __syncthreads();

    // ---- Per-class norm sums (rank 0 only; before min-loop, off the tail) ----
    // |p| = sqrt(2 * sQ)
    if (s == 0) {
        for (int seg = w; seg < 9; seg += NW) {
            int lo, hi; const float* qq;
            if (seg < 4) { qq = sQT; lo = offX[seg + 1]; hi = offX[seg + 2]; }
            else         { qq = sQR; lo = offY[seg - 4]; hi = offY[seg - 3]; }
            float sum = 0.f;
            for (int j = lo + lane; j < hi; j += 32) sum += sqrtf(2.f * qq[j]);
#pragma unroll
            for (int o = 16; o; o >>= 1) sum += __shfl_down_sync(0xffffffffu, sum, o);
            if (lane == 0) {
                if (seg < 4)       mNT[seg + 1] = sum;   // |t| sums, class 1..4
                else if (seg == 4) mNR[0]       = sum;   // |r| sum, class 0
                else               mNR[seg - 4] = sum;   // |r| sums, class 1..4
            }
        }
    }

    // ---- Main work: one item per thread (classes 1..4 only) ----
    // min_j |x-y_j|^2 = |x|^2 + 2*min_j(h_j - x.y_j),  h_j = 0.5|y_j|^2
    const int nA = NPART - offX[1];
    const int nB = NPART - offY[1];
    const int m  = s * BLK + tid;        // 1024 threads per cluster >= nA + nB

    if (m < nA + nB) {
        const bool passA = (m < nA);
        int k = passA ? (offX[1] + m) : (offY[1] + (m - nA));
        const int* off_self  = passA ? offX : offY;
        const int* off_other = passA ? offY : offX;

        int q = 1;
        while (k >= off_self[q + 1]) q++;

        const int jb = off_other[q], je = off_other[q + 1];
        if (jb != je) {
            const float4  x     = passA ? sT[k]  : sR[k];
            const float   xsq   = 2.f * (passA ? sQT[k] : sQR[k]);
            const float4* other = passA ? sR  : sT;
            const float*  hoth  = passA ? sQR : sQT;
            const float nx = -x.x, ny = -x.y, nz = -x.z, nw = -x.w;

            float ms0 = INFINITY, ms1 = INFINITY;
            int j = jb;
            if ((je - jb) & 1) {
                const float4 y = other[j];
                ms0 = fmaf(nx, y.x, fmaf(ny, y.y, fmaf(nz, y.z, fmaf(nw, y.w, hoth[j]))));
                j++;
            }
#pragma unroll 4
            for (; j < je; j += 2) {
                const float4 y0 = other[j];
                const float4 y1 = other[j + 1];
                const float s0 = fmaf(nx, y0.x, fmaf(ny, y0.y, fmaf(nz, y0.z, fmaf(nw, y0.w, hoth[j]))));
                const float s1 = fmaf(nx, y1.x, fmaf(ny, y1.y, fmaf(nz, y1.z, fmaf(nw, y1.w, hoth[j + 1]))));
                ms0 = fminf(ms0, s0);
                ms1 = fminf(ms1, s1);
            }
            const float ms = fminf(ms0, ms1);
            const float d2 = fmaxf(fmaf(2.f, ms, xsq), 0.f);
            atomicAdd(&xacc[(passA ? 0 : 5) + q], sqrtf(d2));
        }
    }

    // ---- Cluster combine: rank 0 reads partner's partials via DSMEM ----
    cluster.sync();                              // xacc of both CTAs complete+visible
    if (s == 0 && tid == 0) {
        const float* pacc = cluster.map_shared_rank(xacc, 1);
        float pa[10];
#pragma unroll
        for (int i = 0; i < 10; i++) pa[i] = pacc[i];  // pipelined DSMEM loads

        float nzsum = 0.f;
#pragma unroll
        for (int q = 1; q < 5; q++) {
            const float cx = (float)(offX[q + 1] - offX[q]);
            const float cy = (float)(offY[q + 1] - offY[q]);
            float per;
            if (cy == 0.f)      per = mNT[q] / fmaxf(1.f, cx);
            else if (cx == 0.f) per = mNR[q] / fmaxf(1.f, cy);
            else                per = 0.5f * ((xacc[q] + pa[q]) / fmaxf(1.f, cy)
                                            + (xacc[5 + q] + pa[5 + q]) / fmaxf(1.f, cx));
            nzsum += per;
        }
        float2 res;
        res.x = nzsum;
        res.y = mNR[0] / fmaxf(1.f, (float)(offY[1] - offY[0]));
        g_batch[b] = res;
        __threadfence();                         // order STG before ticket
        fl = (atomicAdd(&g_ticket, 1) == BATCH - 1);
    }
    cluster.sync();                              // keep partner smem alive for the read
    if (s == 1) return;

    __syncthreads();                             // broadcast fl within rank0 CTA
    if (!fl) return;

    // ---- Last CTA: final combine over 64 batches ----
    __threadfence();                             // acquire all g_batch
    if (tid < BATCH) {
        const float2 vv = __ldcg(&g_batch[tid]);
        snz[tid] = vv.x;
        szz[tid] = vv.y;
    }
    __syncthreads();
    if (tid < 32) {
        float a = snz[tid] + snz[tid + 32];
        float c = szz[tid] + szz[tid + 32];
#pragma unroll
        for (int o = 16; o; o >>= 1) {
            a += __shfl_down_sync(0xffffffffu, a, o);
            c += __shfl_down_sync(0xffffffffu, c, o);
        }
        if (tid == 0) {
            out[0] = a / (float)BATCH;
            if (out_size > 1) out[1] = c / (float)BATCH;
            g_ticket = 0;                        // reset for next graph replay
        }
    }
}

extern "C" void kernel_launch(void* const* d_in, const int* in_sizes, int n_in,
                              void* d_out, int out_size)
{
    const float4* target = (const float4*)d_in[0];
    const float4* reco   = (const float4*)d_in[1];
    const int*    ipid   = (const int*)d_in[2];
    const int*    opid   = (const int*)d_in[3];
    float*        out    = (float*)d_out;
    (void)in_sizes; (void)n_in;

    chamfer_fused<<<GRID, BLK>>>(target, reco, ipid, opid, out, out_size);
}